// round 1
// baseline (speedup 1.0000x reference)
#include <cuda_runtime.h>
#include <math.h>

#define BB 256   // batch
#define NS 32    // spans
#define DD 512   // feature dim

// Scratch (allocation-free rule: __device__ globals)
__device__ float g_A[BB * DD];    // ner span-sums, [b][d], pre-scaled by 1/1024
__device__ float g_FT[DD * BB];   // face span-sums, TRANSPOSED [d][c]
__device__ float g_diag[BB];      // logp[b][b] per row

// ---------------------------------------------------------------------------
// Kernel 1: span reductions. 512 blocks (0..255 ner rows, 256..511 face rows),
// 128 threads, one float4 (4 d-values) per thread, 32-deep sum over spans.
// Pure HBM stream: 33.5 MB read.
// ---------------------------------------------------------------------------
__global__ void reduce_spans(const float* __restrict__ face,
                             const float* __restrict__ ner) {
    const int blk = blockIdx.x;
    const int t   = threadIdx.x;          // 0..127 -> float4 index
    const bool is_ner = (blk < BB);
    const int row = is_ner ? blk : blk - BB;
    const float4* src = reinterpret_cast<const float4*>(
        (is_ner ? ner : face) + (size_t)row * NS * DD);

    float4 s = make_float4(0.f, 0.f, 0.f, 0.f);
#pragma unroll
    for (int n = 0; n < NS; n++) {
        float4 v = src[n * (DD / 4) + t];
        s.x += v.x; s.y += v.y; s.z += v.z; s.w += v.w;
    }

    if (is_ner) {
        const float inv = 1.0f / 1024.0f;   // fold the (1/(N1*N2)) mean here
        s.x *= inv; s.y *= inv; s.z *= inv; s.w *= inv;
        reinterpret_cast<float4*>(g_A + row * DD)[t] = s;
    } else {
        const int d = t * 4;
        g_FT[(d + 0) * BB + row] = s.x;
        g_FT[(d + 1) * BB + row] = s.y;
        g_FT[(d + 2) * BB + row] = s.z;
        g_FT[(d + 3) * BB + row] = s.w;
    }
}

// ---------------------------------------------------------------------------
// Kernel 2: logits GEMM + fused per-row log-sum-exp.
// grid = 128 blocks, each owns rows {2*blk, 2*blk+1}; 256 threads, thread c
// computes logits[row][c]. FT read coalesced per-k; 2 FMA per 4B load.
// Then block-wide max / sum-exp reductions per row -> g_diag.
// ---------------------------------------------------------------------------
__global__ void gemm_lse() {
    const int c  = threadIdx.x;           // column 0..255
    const int b0 = blockIdx.x * 2;
    const int b1 = b0 + 1;

    __shared__ float sA0[DD];
    __shared__ float sA1[DD];
    for (int i = c; i < DD; i += 256) {
        sA0[i] = g_A[b0 * DD + i];
        sA1[i] = g_A[b1 * DD + i];
    }
    __syncthreads();

    float acc0 = 0.f, acc1 = 0.f;
#pragma unroll 16
    for (int k = 0; k < DD; k++) {
        float f = g_FT[k * BB + c];
        acc0 = fmaf(sA0[k], f, acc0);
        acc1 = fmaf(sA1[k], f, acc1);
    }
    // acc0 = logits[b0][c], acc1 = logits[b1][c] (already scaled via A)

    __shared__ float red[8];
    __shared__ float dv[2];
    if (c == b0) dv[0] = acc0;
    if (c == b1) dv[1] = acc1;

    const int lane = c & 31;
    const int warp = c >> 5;

    // ---- row b0: max ----
    float m0 = acc0;
#pragma unroll
    for (int o = 16; o; o >>= 1) m0 = fmaxf(m0, __shfl_xor_sync(0xffffffffu, m0, o));
    if (lane == 0) red[warp] = m0;
    __syncthreads();
    {
        float m = red[0];
#pragma unroll
        for (int i = 1; i < 8; i++) m = fmaxf(m, red[i]);
        m0 = m;
    }
    __syncthreads();

    // ---- row b0: sum exp ----
    float s0 = __expf(acc0 - m0);
#pragma unroll
    for (int o = 16; o; o >>= 1) s0 += __shfl_xor_sync(0xffffffffu, s0, o);
    if (lane == 0) red[warp] = s0;
    __syncthreads();
    {
        float s = red[0];
#pragma unroll
        for (int i = 1; i < 8; i++) s += red[i];
        s0 = s;
    }
    __syncthreads();

    // ---- row b1: max ----
    float m1 = acc1;
#pragma unroll
    for (int o = 16; o; o >>= 1) m1 = fmaxf(m1, __shfl_xor_sync(0xffffffffu, m1, o));
    if (lane == 0) red[warp] = m1;
    __syncthreads();
    {
        float m = red[0];
#pragma unroll
        for (int i = 1; i < 8; i++) m = fmaxf(m, red[i]);
        m1 = m;
    }
    __syncthreads();

    // ---- row b1: sum exp ----
    float s1 = __expf(acc1 - m1);
#pragma unroll
    for (int o = 16; o; o >>= 1) s1 += __shfl_xor_sync(0xffffffffu, s1, o);
    if (lane == 0) red[warp] = s1;
    __syncthreads();
    {
        float s = red[0];
#pragma unroll
        for (int i = 1; i < 8; i++) s += red[i];
        s1 = s;
    }
    __syncthreads();

    if (c == 0) {
        g_diag[b0] = dv[0] - (m0 + logf(s0));
        g_diag[b1] = dv[1] - (m1 + logf(s1));
    }
}

// ---------------------------------------------------------------------------
// Kernel 3: out = -mean_b g_diag[b]. One block, 256 threads.
// ---------------------------------------------------------------------------
__global__ void finalize(float* __restrict__ out) {
    const int t = threadIdx.x;
    float v = g_diag[t];
    const int lane = t & 31;
    const int warp = t >> 5;
    __shared__ float red[8];
#pragma unroll
    for (int o = 16; o; o >>= 1) v += __shfl_xor_sync(0xffffffffu, v, o);
    if (lane == 0) red[warp] = v;
    __syncthreads();
    if (t == 0) {
        float s = red[0];
#pragma unroll
        for (int i = 1; i < 8; i++) s += red[i];
        out[0] = -s * (1.0f / 256.0f);
    }
}

extern "C" void kernel_launch(void* const* d_in, const int* in_sizes, int n_in,
                              void* d_out, int out_size) {
    const float* face = (const float*)d_in[0];  // (256, 32, 512)
    const float* ner  = (const float*)d_in[1];  // (256, 32, 512)
    float* out = (float*)d_out;

    reduce_spans<<<2 * BB, 128>>>(face, ner);
    gemm_lse<<<BB / 2, 256>>>();
    finalize<<<1, 256>>>(out);
}

// round 2
// speedup vs baseline: 1.9167x; 1.9167x over previous
#include <cuda_runtime.h>
#include <math.h>

#define BB 256   // batch
#define NS 32    // spans
#define DD 512   // feature dim

// Scratch (allocation-free rule: __device__ globals)
__device__ float g_A[BB * DD];        // ner span-sums, [b][d], pre-scaled by 1/1024
__device__ float g_FT[DD * BB];       // face span-sums, TRANSPOSED [d][c]
__device__ float g_sum;               // sum of diagonal logp
__device__ unsigned int g_cnt;        // block arrival counter

// ---------------------------------------------------------------------------
// Kernel 1: span reductions. 512 blocks × 512 threads.
// Thread = (d4, span-group): t4 = tid&127 picks one float4 of d, grp = tid>>7
// picks 8 of the 32 spans. 4 partial sums combined in shared memory.
// 262K threads in flight -> DRAM-latency covered.
// ---------------------------------------------------------------------------
__global__ void reduce_spans(const float* __restrict__ face,
                             const float* __restrict__ ner) {
    const int blk = blockIdx.x;
    const int tid = threadIdx.x;
    const int t4  = tid & 127;     // float4 index within row (128 * 4 = 512 d)
    const int grp = tid >> 7;      // span group 0..3 (8 spans each)

    const bool is_ner = (blk < BB);
    const int row = is_ner ? blk : blk - BB;
    const float4* src = reinterpret_cast<const float4*>(
        (is_ner ? ner : face) + (size_t)row * NS * DD);

    float4 s = make_float4(0.f, 0.f, 0.f, 0.f);
#pragma unroll
    for (int n = 0; n < 8; n++) {
        float4 v = src[(grp * 8 + n) * (DD / 4) + t4];
        s.x += v.x; s.y += v.y; s.z += v.z; s.w += v.w;
    }

    __shared__ float4 sp[3][128];
    if (grp > 0) sp[grp - 1][t4] = s;
    __syncthreads();

    if (grp == 0) {
#pragma unroll
        for (int i = 0; i < 3; i++) {
            float4 v = sp[i][t4];
            s.x += v.x; s.y += v.y; s.z += v.z; s.w += v.w;
        }
        if (is_ner) {
            const float inv = 1.0f / 1024.0f;   // fold the 1/(N1*N2) mean
            s.x *= inv; s.y *= inv; s.z *= inv; s.w *= inv;
            reinterpret_cast<float4*>(g_A + row * DD)[t4] = s;
        } else {
            const int d = t4 * 4;
            g_FT[(d + 0) * BB + row] = s.x;
            g_FT[(d + 1) * BB + row] = s.y;
            g_FT[(d + 2) * BB + row] = s.z;
            g_FT[(d + 3) * BB + row] = s.w;
        }
    }

    if (blk == 0 && tid == 0) { g_sum = 0.f; g_cnt = 0u; }
}

// ---------------------------------------------------------------------------
// Kernel 2: logits GEMM + fused per-row log-sum-exp + fused final mean.
// 128 blocks × 1024 threads. Block owns rows {2*blk, 2*blk+1}.
// Thread = (c, q): c = tid&255 is the column, q = tid>>8 is a K-quarter
// (128 of the 512 k's). Quarters combined in smem, then block-wide LSE.
// Last-arriving block writes the scalar output.
// ---------------------------------------------------------------------------
__global__ void gemm_lse_fused(float* __restrict__ out) {
    const int tid = threadIdx.x;
    const int c   = tid & 255;
    const int q   = tid >> 8;            // 0..3
    const int b0  = blockIdx.x * 2;
    const int b1  = b0 + 1;

    __shared__ float sA0[DD];
    __shared__ float sA1[DD];
    for (int i = tid; i < DD; i += 1024) {
        sA0[i] = g_A[b0 * DD + i];
        sA1[i] = g_A[b1 * DD + i];
    }
    __syncthreads();

    float acc0 = 0.f, acc1 = 0.f;
    const int k0 = q * 128;
#pragma unroll 8
    for (int kk = 0; kk < 128; kk++) {
        const int k = k0 + kk;
        float f = g_FT[k * BB + c];
        acc0 = fmaf(sA0[k], f, acc0);
        acc1 = fmaf(sA1[k], f, acc1);
    }

    // combine quarters
    __shared__ float spA[3 * 256];
    __shared__ float spB[3 * 256];
    if (q > 0) {
        spA[(q - 1) * 256 + c] = acc0;
        spB[(q - 1) * 256 + c] = acc1;
    }
    __syncthreads();

    const bool valid = (q == 0);
    float a0 = 0.f, a1 = 0.f;
    if (valid) {
        a0 = acc0 + spA[c] + spA[256 + c] + spA[512 + c];
        a1 = acc1 + spB[c] + spB[256 + c] + spB[512 + c];
    }

    __shared__ float dv[2];
    if (valid && c == b0) dv[0] = a0;
    if (valid && c == b1) dv[1] = a1;

    const int lane = tid & 31;
    const int warp = tid >> 5;
    __shared__ float red[32];
    __shared__ float bc;

    // ---- row b0: max ----
    float m = valid ? a0 : -1e30f;
#pragma unroll
    for (int o = 16; o; o >>= 1) m = fmaxf(m, __shfl_xor_sync(0xffffffffu, m, o));
    if (lane == 0) red[warp] = m;
    __syncthreads();
    if (tid == 0) {
        float mm = red[0];
#pragma unroll
        for (int i = 1; i < 32; i++) mm = fmaxf(mm, red[i]);
        bc = mm;
    }
    __syncthreads();
    const float m0 = bc;
    __syncthreads();

    // ---- row b0: sum exp ----
    float s = valid ? __expf(a0 - m0) : 0.f;
#pragma unroll
    for (int o = 16; o; o >>= 1) s += __shfl_xor_sync(0xffffffffu, s, o);
    if (lane == 0) red[warp] = s;
    __syncthreads();
    if (tid == 0) {
        float ss = red[0];
#pragma unroll
        for (int i = 1; i < 32; i++) ss += red[i];
        bc = ss;
    }
    __syncthreads();
    const float s0 = bc;
    __syncthreads();

    // ---- row b1: max ----
    m = valid ? a1 : -1e30f;
#pragma unroll
    for (int o = 16; o; o >>= 1) m = fmaxf(m, __shfl_xor_sync(0xffffffffu, m, o));
    if (lane == 0) red[warp] = m;
    __syncthreads();
    if (tid == 0) {
        float mm = red[0];
#pragma unroll
        for (int i = 1; i < 32; i++) mm = fmaxf(mm, red[i]);
        bc = mm;
    }
    __syncthreads();
    const float m1 = bc;
    __syncthreads();

    // ---- row b1: sum exp ----
    s = valid ? __expf(a1 - m1) : 0.f;
#pragma unroll
    for (int o = 16; o; o >>= 1) s += __shfl_xor_sync(0xffffffffu, s, o);
    if (lane == 0) red[warp] = s;
    __syncthreads();
    if (tid == 0) {
        float ss = red[0];
#pragma unroll
        for (int i = 1; i < 32; i++) ss += red[i];
        bc = ss;
    }
    __syncthreads();
    const float s1 = bc;

    // ---- fused finalize: accumulate diag logp, last block writes output ----
    if (tid == 0) {
        float logp0 = dv[0] - (m0 + logf(s0));
        float logp1 = dv[1] - (m1 + logf(s1));
        atomicAdd(&g_sum, logp0 + logp1);
        __threadfence();
        unsigned int old = atomicAdd(&g_cnt, 1u);
        if (old == (unsigned int)(gridDim.x - 1)) {
            __threadfence();
            out[0] = -(*(volatile float*)&g_sum) * (1.0f / 256.0f);
        }
    }
}

extern "C" void kernel_launch(void* const* d_in, const int* in_sizes, int n_in,
                              void* d_out, int out_size) {
    const float* face = (const float*)d_in[0];  // (256, 32, 512)
    const float* ner  = (const float*)d_in[1];  // (256, 32, 512)
    float* out = (float*)d_out;

    reduce_spans<<<2 * BB, 512>>>(face, ner);
    gemm_lse_fused<<<BB / 2, 1024>>>(out);
}